// round 2
// baseline (speedup 1.0000x reference)
#include <cuda_runtime.h>
#include <cuda_fp16.h>
#include <cstdint>

#define BB 8
#define NN 1024
#define DD 64
#define HH 32
#define NP 16        // h-pairs
#define DVPAD 72     // padded row stride (words) for transposed dv tile

// Scratch for projected activations (allocation-free rule -> device globals).
__device__ float g_ca[BB * NN * HH];  // cell @ w_k
__device__ float g_dv[BB * NN * HH];  // drug @ w_q + bias

__device__ __forceinline__ __half2 tanh2(__half2 x) {
    uint32_t xi = *reinterpret_cast<uint32_t*>(&x);
    uint32_t r;
    asm("tanh.approx.f16x2 %0, %1;" : "=r"(r) : "r"(xi));
    return *reinterpret_cast<__half2*>(&r);
}

// ---------------------------------------------------------------------------
// Projection kernel: one warp per row, lane = h (f32 output).
// ---------------------------------------------------------------------------
__global__ __launch_bounds__(128) void proj_kernel(
    const float* __restrict__ cell, const float* __restrict__ drug,
    const float* __restrict__ w_q, const float* __restrict__ w_k,
    const float* __restrict__ bias)
{
    int warp = threadIdx.x >> 5;
    int lane = threadIdx.x & 31;
    int row  = blockIdx.x * 4 + warp;          // 0 .. 2*B*N-1
    bool is_drug = row >= BB * NN;
    int r = is_drug ? row - BB * NN : row;
    const float* src = (is_drug ? drug : cell) + r * DD;
    const float* W   = is_drug ? w_q : w_k;    // [D][H] row-major

    float x0 = src[lane];
    float x1 = src[lane + 32];

    float acc = is_drug ? bias[lane] : 0.0f;
#pragma unroll
    for (int d = 0; d < 32; d++) {
        float rd = __shfl_sync(0xFFFFFFFFu, x0, d);
        acc = fmaf(rd, W[d * HH + lane], acc);
    }
#pragma unroll
    for (int d = 0; d < 32; d++) {
        float rd = __shfl_sync(0xFFFFFFFFu, x1, d);
        acc = fmaf(rd, W[(d + 32) * HH + lane], acc);
    }
    (is_drug ? g_dv : g_ca)[r * HH + lane] = acc;
}

// ---------------------------------------------------------------------------
// Co-attention: 64x64 tile/CTA, 4x4/thread, f16x2 tanh (2 tanh per MUFU issue).
// out[b][i][j] = sum_h a[h] * tanh(ca[b][i][h] + dv[b][j][h])
// ---------------------------------------------------------------------------
__global__ __launch_bounds__(256) void coattn_kernel(
    const float* __restrict__ a_vec, float* __restrict__ out)
{
    __shared__ uint4    s_ca4[64][4];          // [row][group], 4 h-pairs per uint4
    __shared__ uint32_t s_dvT[NP][DVPAD];      // [pair][col] transposed, padded
    __shared__ __half2  s_a2[NP];

    int b  = blockIdx.z;
    int i0 = blockIdx.y * 64;
    int j0 = blockIdx.x * 64;
    int tid = threadIdx.x;

    const float* ca = g_ca + (b * NN + i0) * HH;
    const float* dv = g_dv + (b * NN + j0) * HH;

    uint32_t* s_ca_w = reinterpret_cast<uint32_t*>(s_ca4);

    // Stage: 64 rows x 16 h-pairs each for ca (row-major) and dv (transposed).
#pragma unroll
    for (int k = 0; k < 4; k++) {
        int q = tid + k * 256;          // pair index 0..1023
        int row = q >> 4;
        int p = q & 15;
        float2 u = *reinterpret_cast<const float2*>(ca + row * HH + 2 * p);
        float2 v = *reinterpret_cast<const float2*>(dv + row * HH + 2 * p);
        __half2 uh = __floats2half2_rn(u.x, u.y);
        __half2 vh = __floats2half2_rn(v.x, v.y);
        s_ca_w[row * 16 + p] = *reinterpret_cast<uint32_t*>(&uh);
        s_dvT[p][row]        = *reinterpret_cast<uint32_t*>(&vh);
    }
    if (tid < NP) {
        s_a2[tid] = __floats2half2_rn(a_vec[2 * tid], a_vec[2 * tid + 1]);
    }
    __syncthreads();

    int tx = tid & 15;        // j-dimension (4 consecutive cols -> float4 store)
    int ty = tid >> 4;        // i-dimension

    float acc[4][4];
#pragma unroll
    for (int r = 0; r < 4; r++)
#pragma unroll
        for (int c = 0; c < 4; c++) acc[r][c] = 0.0f;

#pragma unroll
    for (int g = 0; g < 4; g++) {              // 4 groups of 4 h-pairs (8 h each)
        uint4 uu[4], vv[4];
#pragma unroll
        for (int r = 0; r < 4; r++) uu[r] = s_ca4[ty * 4 + r][g];
#pragma unroll
        for (int k = 0; k < 4; k++)
            vv[k] = *reinterpret_cast<uint4*>(&s_dvT[g * 4 + k][tx * 4]);

        __half2 gacc[4][4];
#pragma unroll
        for (int k = 0; k < 4; k++) {          // pair within group
            __half2 a2 = s_a2[g * 4 + k];
#pragma unroll
            for (int r = 0; r < 4; r++) {
                uint32_t uw = (k == 0) ? uu[r].x : (k == 1) ? uu[r].y
                            : (k == 2) ? uu[r].z : uu[r].w;
                __half2 u2 = *reinterpret_cast<__half2*>(&uw);
#pragma unroll
                for (int c = 0; c < 4; c++) {
                    uint32_t vw = (r == 0) ? ((c == 0) ? vv[k].x : (c == 1) ? vv[k].y
                                            : (c == 2) ? vv[k].z : vv[k].w)
                                           : ((c == 0) ? vv[k].x : (c == 1) ? vv[k].y
                                            : (c == 2) ? vv[k].z : vv[k].w);
                    __half2 v2 = *reinterpret_cast<__half2*>(&vw);
                    __half2 t2 = tanh2(__hadd2(u2, v2));
                    if (k == 0) gacc[r][c] = __hmul2(a2, t2);
                    else        gacc[r][c] = __hfma2(a2, t2, gacc[r][c]);
                }
            }
        }
        // Spill group accumulators into f32 master accumulators.
#pragma unroll
        for (int r = 0; r < 4; r++)
#pragma unroll
            for (int c = 0; c < 4; c++)
                acc[r][c] += __low2float(gacc[r][c]) + __high2float(gacc[r][c]);
    }

    // Coalesced float4 stores: j = j0 + tx*4 + c
#pragma unroll
    for (int r = 0; r < 4; r++) {
        int i = i0 + ty * 4 + r;
        float4 val = make_float4(acc[r][0], acc[r][1], acc[r][2], acc[r][3]);
        *reinterpret_cast<float4*>(out + ((size_t)b * NN + i) * NN + j0 + tx * 4) = val;
    }
}

extern "C" void kernel_launch(void* const* d_in, const int* in_sizes, int n_in,
                              void* d_out, int out_size)
{
    const float* cell = (const float*)d_in[0];
    const float* drug = (const float*)d_in[1];
    const float* w_q  = (const float*)d_in[2];
    const float* w_k  = (const float*)d_in[3];
    const float* bias = (const float*)d_in[4];
    const float* a    = (const float*)d_in[5];
    float* out = (float*)d_out;

    proj_kernel<<<(2 * BB * NN) / 4, 128>>>(cell, drug, w_q, w_k, bias);

    dim3 grid(NN / 64, NN / 64, BB);
    coattn_kernel<<<grid, 256>>>(a, out);
}

// round 3
// speedup vs baseline: 1.0296x; 1.0296x over previous
#include <cuda_runtime.h>
#include <cstdint>

#define BB 8
#define NN 1024
#define DD 64
#define HH 32
#define HA 18      // h < HA: MUFU tanh path (raw values staged)
#define PA 9       // h-pair threshold (HA/2)

// Scratch (allocation-free rule -> device globals).
// h < HA: raw projection; h >= HA: tanh(projection).
__device__ float g_ca[BB * NN * HH];
__device__ float g_dv[BB * NN * HH];

using u64 = unsigned long long;

__device__ __forceinline__ u64 f2_add(u64 a, u64 b) {
    u64 r; asm("add.rn.f32x2 %0,%1,%2;" : "=l"(r) : "l"(a), "l"(b)); return r;
}
__device__ __forceinline__ u64 f2_mul(u64 a, u64 b) {
    u64 r; asm("mul.rn.f32x2 %0,%1,%2;" : "=l"(r) : "l"(a), "l"(b)); return r;
}
__device__ __forceinline__ u64 f2_fma(u64 a, u64 b, u64 c) {
    u64 r; asm("fma.rn.f32x2 %0,%1,%2,%3;" : "=l"(r) : "l"(a), "l"(b), "l"(c)); return r;
}
__device__ __forceinline__ u64 pack2(float lo, float hi) {
    u64 r; asm("mov.b64 %0,{%1,%2};" : "=l"(r) : "f"(lo), "f"(hi)); return r;
}
__device__ __forceinline__ void unpack2(u64 v, float& lo, float& hi) {
    asm("mov.b64 {%0,%1},%2;" : "=f"(lo), "=f"(hi) : "l"(v));
}
__device__ __forceinline__ float tanh_a(float x) {
    float r; asm("tanh.approx.f32 %0,%1;" : "=f"(r) : "f"(x)); return r;
}

#define ONE2 0x3F8000003F800000ULL

// ---------------------------------------------------------------------------
// Projection: one warp per row, lane = h. h<HA raw, h>=HA tanh'd.
// ---------------------------------------------------------------------------
__global__ __launch_bounds__(128) void proj_kernel(
    const float* __restrict__ cell, const float* __restrict__ drug,
    const float* __restrict__ w_q, const float* __restrict__ w_k,
    const float* __restrict__ bias)
{
    int warp = threadIdx.x >> 5;
    int lane = threadIdx.x & 31;
    int row  = blockIdx.x * 4 + warp;          // 0 .. 2*B*N-1
    bool is_drug = row >= BB * NN;
    int r = is_drug ? row - BB * NN : row;
    const float* src = (is_drug ? drug : cell) + r * DD;
    const float* W   = is_drug ? w_q : w_k;    // [D][H] row-major

    float x0 = src[lane];
    float x1 = src[lane + 32];

    float acc = is_drug ? bias[lane] : 0.0f;
#pragma unroll
    for (int d = 0; d < 32; d++) {
        float rd = __shfl_sync(0xFFFFFFFFu, x0, d);
        acc = fmaf(rd, W[d * HH + lane], acc);
    }
#pragma unroll
    for (int d = 0; d < 32; d++) {
        float rd = __shfl_sync(0xFFFFFFFFu, x1, d);
        acc = fmaf(rd, W[(d + 32) * HH + lane], acc);
    }
    if (lane >= HA) acc = tanh_a(acc);
    (is_drug ? g_dv : g_ca)[r * HH + lane] = acc;
}

// ---------------------------------------------------------------------------
// Co-attention: 64x64 tile/CTA, 4x4/thread, h packed in pairs (f32x2).
// h <  HA: e = u+v; tanh on MUFU; acc += a*t
// h >= HA: tanh(u+v) = (tu+tv)/(1+tu*tv), reciprocal via bit-seed + 2 Newton
//          iterations on the FMA pipe (a pre-negated, carries the -z sign).
// ---------------------------------------------------------------------------
__global__ __launch_bounds__(256, 2) void coattn_kernel(
    const float* __restrict__ a_vec, float* __restrict__ out)
{
    __shared__ float s_u[64][36];      // [i-row][h], padded
    __shared__ u64   s_v2[16][66];     // [h-pair][j-col] packed (h0,h1), padded
    __shared__ u64   s_a2[16];

    int b  = blockIdx.z;
    int i0 = blockIdx.y * 64;
    int j0 = blockIdx.x * 64;
    int tid = threadIdx.x;

    const float* ca = g_ca + (b * NN + i0) * HH;
    const float* dv = g_dv + (b * NN + j0) * HH;

#pragma unroll
    for (int k = 0; k < 2; k++) {
        int idx = tid + k * 256;       // 0..511
        int row = idx >> 3, g = idx & 7;
        float4 uu = *reinterpret_cast<const float4*>(ca + row * HH + 4 * g);
        *reinterpret_cast<float4*>(&s_u[row][4 * g]) = uu;
        float4 vv = *reinterpret_cast<const float4*>(dv + row * HH + 4 * g);
        s_v2[2 * g][row]     = pack2(vv.x, vv.y);
        s_v2[2 * g + 1][row] = pack2(vv.z, vv.w);
    }
    if (tid < 16) {
        float alo = a_vec[2 * tid], ahi = a_vec[2 * tid + 1];
        if (tid >= PA) { alo = -alo; ahi = -ahi; }   // folds r = -s*z sign
        s_a2[tid] = pack2(alo, ahi);
    }
    __syncthreads();

    int tx = tid & 15;        // j quad
    int ty = tid >> 4;        // i quad

    u64 acc[4][4];
#pragma unroll
    for (int r = 0; r < 4; r++)
#pragma unroll
        for (int c = 0; c < 4; c++) acc[r][c] = 0ULL;

#pragma unroll
    for (int g = 0; g < 8; g++) {                 // h-groups of 4
        float4 u4[4];
#pragma unroll
        for (int r = 0; r < 4; r++)
            u4[r] = *reinterpret_cast<float4*>(&s_u[ty * 4 + r][4 * g]);

#pragma unroll
        for (int sp = 0; sp < 2; sp++) {          // sub-pair within group
            const int p = 2 * g + sp;             // h-pair index (compile-time)
            u64 a2 = s_a2[p];
            ulonglong2 va = *reinterpret_cast<ulonglong2*>(&s_v2[p][tx * 4]);
            ulonglong2 vb = *reinterpret_cast<ulonglong2*>(&s_v2[p][tx * 4 + 2]);
            u64 v2[4] = {va.x, va.y, vb.x, vb.y};

#pragma unroll
            for (int r = 0; r < 4; r++) {
                u64 u2 = sp ? pack2(u4[r].z, u4[r].w) : pack2(u4[r].x, u4[r].y);
#pragma unroll
                for (int c = 0; c < 4; c++) {
                    u64 s2 = f2_add(u2, v2[c]);
                    if (p < PA) {
                        float lo, hi; unpack2(s2, lo, hi);
                        u64 t2 = pack2(tanh_a(lo), tanh_a(hi));
                        acc[r][c] = f2_fma(a2, t2, acc[r][c]);
                    } else {
                        u64 d2 = f2_fma(u2, v2[c], ONE2);          // d = 1+tu*tv
                        float dl, dh; unpack2(d2, dl, dh);
                        u64 z = pack2(                              // z0 = -1/d seed
                            __uint_as_float(0xFEF311C3u - __float_as_uint(dl)),
                            __uint_as_float(0xFEF311C3u - __float_as_uint(dh)));
                        u64 e  = f2_fma(d2, z, ONE2);               // e0 = 1 - d*y0
                        z      = f2_fma(z, e, z);                   // -y1
                        u64 ee = f2_mul(e, e);                      // e0^2
                        z      = f2_fma(z, ee, z);                  // -y2
                        u64 pp = f2_mul(s2, z);                     // -s/d
                        acc[r][c] = f2_fma(a2, pp, acc[r][c]);      // a2 pre-negated
                    }
                }
            }
        }
    }

    // Fold h0/h1 halves, coalesced float4 stores.
#pragma unroll
    for (int r = 0; r < 4; r++) {
        float o[4];
#pragma unroll
        for (int c = 0; c < 4; c++) {
            float lo, hi; unpack2(acc[r][c], lo, hi);
            o[c] = lo + hi;
        }
        int i = i0 + ty * 4 + r;
        *reinterpret_cast<float4*>(out + ((size_t)b * NN + i) * NN + j0 + tx * 4) =
            make_float4(o[0], o[1], o[2], o[3]);
    }
}

extern "C" void kernel_launch(void* const* d_in, const int* in_sizes, int n_in,
                              void* d_out, int out_size)
{
    const float* cell = (const float*)d_in[0];
    const float* drug = (const float*)d_in[1];
    const float* w_q  = (const float*)d_in[2];
    const float* w_k  = (const float*)d_in[3];
    const float* bias = (const float*)d_in[4];
    const float* a    = (const float*)d_in[5];
    float* out = (float*)d_out;

    proj_kernel<<<(2 * BB * NN) / 4, 128>>>(cell, drug, w_q, w_k, bias);

    dim3 grid(NN / 64, NN / 64, BB);
    coattn_kernel<<<grid, 256>>>(a, out);
}

// round 4
// speedup vs baseline: 1.0609x; 1.0305x over previous
#include <cuda_runtime.h>
#include <cstdint>

#define BB 8
#define NN 1024
#define DD 64
#define HH 32
#define HA 18      // h < HA: MUFU tanh path (raw values staged); h >= HA: Newton path (tanh'd staged)

// Scratch (allocation-free rule -> device globals).
__device__ float g_ca[BB * NN * HH];
__device__ float g_dv[BB * NN * HH];

using u64 = unsigned long long;

__device__ __forceinline__ u64 f2_add(u64 a, u64 b) {
    u64 r; asm("add.rn.f32x2 %0,%1,%2;" : "=l"(r) : "l"(a), "l"(b)); return r;
}
__device__ __forceinline__ u64 f2_mul(u64 a, u64 b) {
    u64 r; asm("mul.rn.f32x2 %0,%1,%2;" : "=l"(r) : "l"(a), "l"(b)); return r;
}
__device__ __forceinline__ u64 f2_fma(u64 a, u64 b, u64 c) {
    u64 r; asm("fma.rn.f32x2 %0,%1,%2,%3;" : "=l"(r) : "l"(a), "l"(b), "l"(c)); return r;
}
__device__ __forceinline__ u64 pack2(float lo, float hi) {
    u64 r; asm("mov.b64 %0,{%1,%2};" : "=l"(r) : "f"(lo), "f"(hi)); return r;
}
__device__ __forceinline__ void unpack2(u64 v, float& lo, float& hi) {
    asm("mov.b64 {%0,%1},%2;" : "=f"(lo), "=f"(hi) : "l"(v));
}
__device__ __forceinline__ float tanh_a(float x) {
    float r; asm("tanh.approx.f32 %0,%1;" : "=f"(r) : "f"(x)); return r;
}

#define ONE2 0x3F8000003F800000ULL

// ---------------------------------------------------------------------------
// Projection: one warp per row, lane = h. h<HA raw, h>=HA tanh'd.
// ---------------------------------------------------------------------------
__global__ __launch_bounds__(128) void proj_kernel(
    const float* __restrict__ cell, const float* __restrict__ drug,
    const float* __restrict__ w_q, const float* __restrict__ w_k,
    const float* __restrict__ bias)
{
    int warp = threadIdx.x >> 5;
    int lane = threadIdx.x & 31;
    int row  = blockIdx.x * 4 + warp;          // 0 .. 2*B*N-1
    bool is_drug = row >= BB * NN;
    int r = is_drug ? row - BB * NN : row;
    const float* src = (is_drug ? drug : cell) + r * DD;
    const float* W   = is_drug ? w_q : w_k;    // [D][H] row-major

    float x0 = src[lane];
    float x1 = src[lane + 32];

    float acc = is_drug ? bias[lane] : 0.0f;
#pragma unroll
    for (int d = 0; d < 32; d++) {
        float rd = __shfl_sync(0xFFFFFFFFu, x0, d);
        acc = fmaf(rd, W[d * HH + lane], acc);
    }
#pragma unroll
    for (int d = 0; d < 32; d++) {
        float rd = __shfl_sync(0xFFFFFFFFu, x1, d);
        acc = fmaf(rd, W[(d + 32) * HH + lane], acc);
    }
    if (lane >= HA) acc = tanh_a(acc);
    (is_drug ? g_dv : g_ca)[r * HH + lane] = acc;
}

// ---------------------------------------------------------------------------
// Co-attention: 64x64 tile/CTA, 4x4 outputs/thread, accumulators packed over
// the j-dimension (4x2 f32x2). Per-h scalar loop, fully unrolled.
// h <  HA: e = u+v; tanh on MUFU; acc += a*t
// h >= HA: tanh(u+v) = (tu+tv)/(1+tu*tv), reciprocal via bit-seed + 2 Newton
//          iterations on the FMA pipe (a pre-negated, carries the -z sign).
// ---------------------------------------------------------------------------
__global__ __launch_bounds__(256, 4) void coattn_kernel(
    const float* __restrict__ a_vec, float* __restrict__ out)
{
    __shared__ float s_u[64][36];      // [i-row][h], padded (16B-aligned rows)
    __shared__ float s_v[HH][68];      // [h][j-col] transposed, padded (16B-aligned)
    __shared__ u64   s_a2[HH];         // (a_h, a_h), negated for h >= HA

    int b  = blockIdx.z;
    int i0 = blockIdx.y * 64;
    int j0 = blockIdx.x * 64;
    int tid = threadIdx.x;

    const float* ca = g_ca + (b * NN + i0) * HH;
    const float* dv = g_dv + (b * NN + j0) * HH;

#pragma unroll
    for (int k = 0; k < 2; k++) {
        int idx = tid + k * 256;       // 0..511
        int row = idx >> 3, g = idx & 7;
        float4 uu = *reinterpret_cast<const float4*>(ca + row * HH + 4 * g);
        *reinterpret_cast<float4*>(&s_u[row][4 * g]) = uu;
        float4 vv = *reinterpret_cast<const float4*>(dv + row * HH + 4 * g);
        s_v[4 * g + 0][row] = vv.x;
        s_v[4 * g + 1][row] = vv.y;
        s_v[4 * g + 2][row] = vv.z;
        s_v[4 * g + 3][row] = vv.w;
    }
    if (tid < HH) {
        float av = a_vec[tid];
        if (tid >= HA) av = -av;       // folds r = -s*z sign on Newton path
        s_a2[tid] = pack2(av, av);
    }
    __syncthreads();

    int tx = tid & 15;        // j quad (4 consecutive cols -> float4 store)
    int ty = tid >> 4;        // i quad

    u64 acc[4][2];
#pragma unroll
    for (int r = 0; r < 4; r++) { acc[r][0] = 0ULL; acc[r][1] = 0ULL; }

#pragma unroll
    for (int g = 0; g < 8; g++) {                 // h-groups of 4
        float4 u4[4];
#pragma unroll
        for (int r = 0; r < 4; r++)
            u4[r] = *reinterpret_cast<float4*>(&s_u[ty * 4 + r][4 * g]);

#pragma unroll
        for (int k = 0; k < 4; k++) {
            const int h = 4 * g + k;              // compile-time
            float4 vv = *reinterpret_cast<float4*>(&s_v[h][tx * 4]);
            u64 v2[2] = { pack2(vv.x, vv.y), pack2(vv.z, vv.w) };
            u64 a2 = s_a2[h];

#pragma unroll
            for (int r = 0; r < 4; r++) {
                float us = (k == 0) ? u4[r].x : (k == 1) ? u4[r].y
                         : (k == 2) ? u4[r].z : u4[r].w;
                u64 up = pack2(us, us);
#pragma unroll
                for (int cp = 0; cp < 2; cp++) {
                    u64 s2 = f2_add(up, v2[cp]);
                    if (h < HA) {
                        float lo, hi; unpack2(s2, lo, hi);
                        u64 t2 = pack2(tanh_a(lo), tanh_a(hi));
                        acc[r][cp] = f2_fma(a2, t2, acc[r][cp]);
                    } else {
                        u64 d2 = f2_fma(up, v2[cp], ONE2);          // d = 1+tu*tv
                        float dl, dh; unpack2(d2, dl, dh);
                        u64 z = pack2(                               // z0 = -1/d seed
                            __uint_as_float(0xFEF311C3u - __float_as_uint(dl)),
                            __uint_as_float(0xFEF311C3u - __float_as_uint(dh)));
                        u64 e  = f2_fma(d2, z, ONE2);                // e0 = 1 - d*y0
                        z      = f2_fma(z, e, z);                    // -y1
                        u64 ee = f2_mul(e, e);                       // e0^2
                        z      = f2_fma(z, ee, z);                   // -y2
                        u64 pp = f2_mul(s2, z);                      // -s/d
                        acc[r][cp] = f2_fma(a2, pp, acc[r][cp]);     // a2 pre-negated
                    }
                }
            }
        }
    }

    // Stores come straight from the j-packed accumulators (no h-fold needed).
#pragma unroll
    for (int r = 0; r < 4; r++) {
        float o0, o1, o2, o3;
        unpack2(acc[r][0], o0, o1);
        unpack2(acc[r][1], o2, o3);
        int i = i0 + ty * 4 + r;
        *reinterpret_cast<float4*>(out + ((size_t)b * NN + i) * NN + j0 + tx * 4) =
            make_float4(o0, o1, o2, o3);
    }
}

extern "C" void kernel_launch(void* const* d_in, const int* in_sizes, int n_in,
                              void* d_out, int out_size)
{
    const float* cell = (const float*)d_in[0];
    const float* drug = (const float*)d_in[1];
    const float* w_q  = (const float*)d_in[2];
    const float* w_k  = (const float*)d_in[3];
    const float* bias = (const float*)d_in[4];
    const float* a    = (const float*)d_in[5];
    float* out = (float*)d_out;

    proj_kernel<<<(2 * BB * NN) / 4, 128>>>(cell, drug, w_q, w_k, bias);

    dim3 grid(NN / 64, NN / 64, BB);
    coattn_kernel<<<grid, 256>>>(a, out);
}

// round 5
// speedup vs baseline: 1.2460x; 1.1745x over previous
#include <cuda_runtime.h>
#include <cstdint>

#define BB 8
#define NN 1024
#define DD 64
#define HH 32

// Interleaved path assignment: 18 MUFU h's spread evenly among 32.
// is_mufu(h) <=> floor((h+1)*18/32) > floor(h*18/32)
#define IS_MUFU(h) ((((h) + 1) * 18 >> 5) > ((h) * 18 >> 5))

// Scratch (allocation-free rule -> device globals).
// MUFU h's: raw projection; Newton h's: tanh(projection).
__device__ float g_ca[BB * NN * HH];
__device__ float g_dv[BB * NN * HH];

using u64 = unsigned long long;

__device__ __forceinline__ u64 f2_add(u64 a, u64 b) {
    u64 r; asm("add.rn.f32x2 %0,%1,%2;" : "=l"(r) : "l"(a), "l"(b)); return r;
}
__device__ __forceinline__ u64 f2_mul(u64 a, u64 b) {
    u64 r; asm("mul.rn.f32x2 %0,%1,%2;" : "=l"(r) : "l"(a), "l"(b)); return r;
}
__device__ __forceinline__ u64 f2_fma(u64 a, u64 b, u64 c) {
    u64 r; asm("fma.rn.f32x2 %0,%1,%2,%3;" : "=l"(r) : "l"(a), "l"(b), "l"(c)); return r;
}
__device__ __forceinline__ u64 pack2(float lo, float hi) {
    u64 r; asm("mov.b64 %0,{%1,%2};" : "=l"(r) : "f"(lo), "f"(hi)); return r;
}
__device__ __forceinline__ void unpack2(u64 v, float& lo, float& hi) {
    asm("mov.b64 {%0,%1},%2;" : "=f"(lo), "=f"(hi) : "l"(v));
}
__device__ __forceinline__ float tanh_a(float x) {
    float r; asm("tanh.approx.f32 %0,%1;" : "=f"(r) : "f"(x)); return r;
}

#define ONE2 0x3F8000003F800000ULL

// ---------------------------------------------------------------------------
// Projection: one warp per row, lane = h. MUFU-h raw, Newton-h tanh'd.
// ---------------------------------------------------------------------------
__global__ __launch_bounds__(128) void proj_kernel(
    const float* __restrict__ cell, const float* __restrict__ drug,
    const float* __restrict__ w_q, const float* __restrict__ w_k,
    const float* __restrict__ bias)
{
    int warp = threadIdx.x >> 5;
    int lane = threadIdx.x & 31;
    int row  = blockIdx.x * 4 + warp;          // 0 .. 2*B*N-1
    bool is_drug = row >= BB * NN;
    int r = is_drug ? row - BB * NN : row;
    const float* src = (is_drug ? drug : cell) + r * DD;
    const float* W   = is_drug ? w_q : w_k;    // [D][H] row-major

    float x0 = src[lane];
    float x1 = src[lane + 32];

    float acc = is_drug ? bias[lane] : 0.0f;
#pragma unroll
    for (int d = 0; d < 32; d++) {
        float rd = __shfl_sync(0xFFFFFFFFu, x0, d);
        acc = fmaf(rd, W[d * HH + lane], acc);
    }
#pragma unroll
    for (int d = 0; d < 32; d++) {
        float rd = __shfl_sync(0xFFFFFFFFu, x1, d);
        acc = fmaf(rd, W[(d + 32) * HH + lane], acc);
    }
    if (!IS_MUFU(lane)) acc = tanh_a(acc);     // Newton lanes store tanh'd value
    (is_drug ? g_dv : g_ca)[r * HH + lane] = acc;
}

// ---------------------------------------------------------------------------
// Co-attention: 64x64 tile/CTA, 4x4 outputs/thread, accumulators packed over
// the j-dimension (4x2 f32x2). Per-h fully unrolled; MUFU and Newton h's are
// interleaved so the MUFU and FMA pipes stay loaded simultaneously.
// MUFU h:   e = u+v; tanh.approx on MUFU; acc += a*t
// Newton h: tanh(u+v) = (tu+tv)/(1+tu*tv), reciprocal via bit-seed + 2 Newton
//           iterations on the FMA pipe (a pre-negated, carries the -z sign).
// ---------------------------------------------------------------------------
__global__ __launch_bounds__(256, 4) void coattn_kernel(
    const float* __restrict__ a_vec, float* __restrict__ out)
{
    __shared__ float s_u[64][36];      // [i-row][h], padded (16B-aligned rows)
    __shared__ float s_v[HH][68];      // [h][j-col] transposed, padded
    __shared__ u64   s_a2[HH];         // (a_h, a_h), negated for Newton h

    int b  = blockIdx.z;
    int i0 = blockIdx.y * 64;
    int j0 = blockIdx.x * 64;
    int tid = threadIdx.x;

    const float* ca = g_ca + (b * NN + i0) * HH;
    const float* dv = g_dv + (b * NN + j0) * HH;

#pragma unroll
    for (int k = 0; k < 2; k++) {
        int idx = tid + k * 256;       // 0..511
        int row = idx >> 3, g = idx & 7;
        float4 uu = *reinterpret_cast<const float4*>(ca + row * HH + 4 * g);
        *reinterpret_cast<float4*>(&s_u[row][4 * g]) = uu;
        float4 vv = *reinterpret_cast<const float4*>(dv + row * HH + 4 * g);
        s_v[4 * g + 0][row] = vv.x;
        s_v[4 * g + 1][row] = vv.y;
        s_v[4 * g + 2][row] = vv.z;
        s_v[4 * g + 3][row] = vv.w;
    }
    if (tid < HH) {
        float av = a_vec[tid];
        if (!IS_MUFU(tid)) av = -av;   // folds r = -s*z sign on Newton path
        s_a2[tid] = pack2(av, av);
    }
    __syncthreads();

    int tx = tid & 15;        // j quad (4 consecutive cols -> float4 store)
    int ty = tid >> 4;        // i quad

    u64 acc[4][2];
#pragma unroll
    for (int r = 0; r < 4; r++) { acc[r][0] = 0ULL; acc[r][1] = 0ULL; }

#pragma unroll
    for (int g = 0; g < 8; g++) {                 // h-groups of 4 (mixed paths)
        float4 u4[4];
#pragma unroll
        for (int r = 0; r < 4; r++)
            u4[r] = *reinterpret_cast<float4*>(&s_u[ty * 4 + r][4 * g]);

#pragma unroll
        for (int k = 0; k < 4; k++) {
            const int h = 4 * g + k;              // compile-time
            float4 vv = *reinterpret_cast<float4*>(&s_v[h][tx * 4]);
            u64 v2[2] = { pack2(vv.x, vv.y), pack2(vv.z, vv.w) };
            u64 a2 = s_a2[h];

#pragma unroll
            for (int r = 0; r < 4; r++) {
                float us = (k == 0) ? u4[r].x : (k == 1) ? u4[r].y
                         : (k == 2) ? u4[r].z : u4[r].w;
                u64 up = pack2(us, us);
#pragma unroll
                for (int cp = 0; cp < 2; cp++) {
                    u64 s2 = f2_add(up, v2[cp]);
                    if (IS_MUFU(h)) {
                        float lo, hi; unpack2(s2, lo, hi);
                        u64 t2 = pack2(tanh_a(lo), tanh_a(hi));
                        acc[r][cp] = f2_fma(a2, t2, acc[r][cp]);
                    } else {
                        u64 d2 = f2_fma(up, v2[cp], ONE2);          // d = 1+tu*tv
                        float dl, dh; unpack2(d2, dl, dh);
                        u64 z = pack2(                               // z0 = -1/d seed
                            __uint_as_float(0xFEF311C3u - __float_as_uint(dl)),
                            __uint_as_float(0xFEF311C3u - __float_as_uint(dh)));
                        u64 e  = f2_fma(d2, z, ONE2);                // e0 = 1 - d*y0
                        z      = f2_fma(z, e, z);                    // -y1
                        u64 ee = f2_mul(e, e);                       // e0^2
                        z      = f2_fma(z, ee, z);                   // -y2
                        u64 pp = f2_mul(s2, z);                      // -s/d
                        acc[r][cp] = f2_fma(a2, pp, acc[r][cp]);     // a2 pre-negated
                    }
                }
            }
        }
    }

    // Stores come straight from the j-packed accumulators.
#pragma unroll
    for (int r = 0; r < 4; r++) {
        float o0, o1, o2, o3;
        unpack2(acc[r][0], o0, o1);
        unpack2(acc[r][1], o2, o3);
        int i = i0 + ty * 4 + r;
        *reinterpret_cast<float4*>(out + ((size_t)b * NN + i) * NN + j0 + tx * 4) =
            make_float4(o0, o1, o2, o3);
    }
}

extern "C" void kernel_launch(void* const* d_in, const int* in_sizes, int n_in,
                              void* d_out, int out_size)
{
    const float* cell = (const float*)d_in[0];
    const float* drug = (const float*)d_in[1];
    const float* w_q  = (const float*)d_in[2];
    const float* w_k  = (const float*)d_in[3];
    const float* bias = (const float*)d_in[4];
    const float* a    = (const float*)d_in[5];
    float* out = (float*)d_out;

    proj_kernel<<<(2 * BB * NN) / 4, 128>>>(cell, drug, w_q, w_k, bias);

    dim3 grid(NN / 64, NN / 64, BB);
    coattn_kernel<<<grid, 256>>>(a, out);
}

// round 6
// speedup vs baseline: 1.2522x; 1.0050x over previous
#include <cuda_runtime.h>
#include <cstdint>

#define BB 8
#define NN 1024
#define DD 64
#define HH 32

// Interleaved path assignment: 17 MUFU h's spread evenly among 32.
#define IS_MUFU(h) ((((h) + 1) * 17 >> 5) > ((h) * 17 >> 5))

// Scratch (allocation-free rule -> device globals).
// MUFU h's: raw projection; Newton h's: tanh(projection).
__device__ float g_ca[BB * NN * HH];
__device__ float g_dv[BB * NN * HH];

using u64 = unsigned long long;

__device__ __forceinline__ u64 f2_add(u64 a, u64 b) {
    u64 r; asm("add.rn.f32x2 %0,%1,%2;" : "=l"(r) : "l"(a), "l"(b)); return r;
}
__device__ __forceinline__ u64 f2_mul(u64 a, u64 b) {
    u64 r; asm("mul.rn.f32x2 %0,%1,%2;" : "=l"(r) : "l"(a), "l"(b)); return r;
}
__device__ __forceinline__ u64 f2_fma(u64 a, u64 b, u64 c) {
    u64 r; asm("fma.rn.f32x2 %0,%1,%2,%3;" : "=l"(r) : "l"(a), "l"(b), "l"(c)); return r;
}
__device__ __forceinline__ u64 pack2(float lo, float hi) {
    u64 r; asm("mov.b64 %0,{%1,%2};" : "=l"(r) : "f"(lo), "f"(hi)); return r;
}
__device__ __forceinline__ void unpack2(u64 v, float& lo, float& hi) {
    asm("mov.b64 {%0,%1},%2;" : "=f"(lo), "=f"(hi) : "l"(v));
}
__device__ __forceinline__ float tanh_a(float x) {
    float r; asm("tanh.approx.f32 %0,%1;" : "=f"(r) : "f"(x)); return r;
}

#define ONE2 0x3F8000003F800000ULL

// ---------------------------------------------------------------------------
// Projection: one warp per row, lane = h. MUFU-h raw, Newton-h tanh'd.
// ---------------------------------------------------------------------------
__global__ __launch_bounds__(128) void proj_kernel(
    const float* __restrict__ cell, const float* __restrict__ drug,
    const float* __restrict__ w_q, const float* __restrict__ w_k,
    const float* __restrict__ bias)
{
    int warp = threadIdx.x >> 5;
    int lane = threadIdx.x & 31;
    int row  = blockIdx.x * 4 + warp;          // 0 .. 2*B*N-1
    bool is_drug = row >= BB * NN;
    int r = is_drug ? row - BB * NN : row;
    const float* src = (is_drug ? drug : cell) + r * DD;
    const float* W   = is_drug ? w_q : w_k;    // [D][H] row-major

    float x0 = src[lane];
    float x1 = src[lane + 32];

    float acc = is_drug ? bias[lane] : 0.0f;
#pragma unroll
    for (int d = 0; d < 32; d++) {
        float rd = __shfl_sync(0xFFFFFFFFu, x0, d);
        acc = fmaf(rd, W[d * HH + lane], acc);
    }
#pragma unroll
    for (int d = 0; d < 32; d++) {
        float rd = __shfl_sync(0xFFFFFFFFu, x1, d);
        acc = fmaf(rd, W[(d + 32) * HH + lane], acc);
    }
    if (!IS_MUFU(lane)) acc = tanh_a(acc);     // Newton lanes store tanh'd value
    (is_drug ? g_dv : g_ca)[r * HH + lane] = acc;
}

// ---------------------------------------------------------------------------
// Co-attention: 64x64 tile/CTA, 4x4 outputs/thread, accumulators packed over
// the j-dimension (4x2 f32x2). h processed in groups of 2 (float2 u staging,
// lower register pressure -> 5 CTAs/SM). MUFU and Newton h's interleaved so
// both pipes stay loaded.
// MUFU h:   e = u+v; tanh.approx on MUFU; acc += a*t
// Newton h: tanh(u+v) = (tu+tv)/(1+tu*tv); reciprocal = bit-seed + one fused
//           cubic correction z*(1+e+e^2) on the FMA pipe (err ~ e0^3).
// ---------------------------------------------------------------------------
__global__ __launch_bounds__(256, 5) void coattn_kernel(
    const float* __restrict__ a_vec, float* __restrict__ out)
{
    __shared__ float s_u[64][36];      // [i-row][h], padded (16B-aligned rows)
    __shared__ float s_v[HH][68];      // [h][j-col] transposed, padded
    __shared__ u64   s_a2[HH];         // (a_h, a_h), negated for Newton h

    int b  = blockIdx.z;
    int i0 = blockIdx.y * 64;
    int j0 = blockIdx.x * 64;
    int tid = threadIdx.x;

    const float* ca = g_ca + (b * NN + i0) * HH;
    const float* dv = g_dv + (b * NN + j0) * HH;

#pragma unroll
    for (int k = 0; k < 2; k++) {
        int idx = tid + k * 256;       // 0..511
        int row = idx >> 3, g = idx & 7;
        float4 uu = *reinterpret_cast<const float4*>(ca + row * HH + 4 * g);
        *reinterpret_cast<float4*>(&s_u[row][4 * g]) = uu;
        float4 vv = *reinterpret_cast<const float4*>(dv + row * HH + 4 * g);
        s_v[4 * g + 0][row] = vv.x;
        s_v[4 * g + 1][row] = vv.y;
        s_v[4 * g + 2][row] = vv.z;
        s_v[4 * g + 3][row] = vv.w;
    }
    if (tid < HH) {
        float av = a_vec[tid];
        if (!IS_MUFU(tid)) av = -av;   // folds r = -s*z sign on Newton path
        s_a2[tid] = pack2(av, av);
    }
    __syncthreads();

    int tx = tid & 15;        // j quad (4 consecutive cols -> float4 store)
    int ty = tid >> 4;        // i quad

    u64 acc[4][2];
#pragma unroll
    for (int r = 0; r < 4; r++) { acc[r][0] = 0ULL; acc[r][1] = 0ULL; }

#pragma unroll
    for (int g = 0; g < 16; g++) {                // h-groups of 2 (mixed paths)
        float2 u2r[4];
#pragma unroll
        for (int r = 0; r < 4; r++)
            u2r[r] = *reinterpret_cast<float2*>(&s_u[ty * 4 + r][2 * g]);

#pragma unroll
        for (int k = 0; k < 2; k++) {
            const int h = 2 * g + k;              // compile-time
            float4 vv = *reinterpret_cast<float4*>(&s_v[h][tx * 4]);
            u64 v2[2] = { pack2(vv.x, vv.y), pack2(vv.z, vv.w) };
            u64 a2 = s_a2[h];

#pragma unroll
            for (int r = 0; r < 4; r++) {
                float us = k ? u2r[r].y : u2r[r].x;
                u64 up = pack2(us, us);
#pragma unroll
                for (int cp = 0; cp < 2; cp++) {
                    u64 s2 = f2_add(up, v2[cp]);
                    if (IS_MUFU(h)) {
                        float lo, hi; unpack2(s2, lo, hi);
                        u64 t2 = pack2(tanh_a(lo), tanh_a(hi));
                        acc[r][cp] = f2_fma(a2, t2, acc[r][cp]);
                    } else {
                        u64 d2 = f2_fma(up, v2[cp], ONE2);          // d = 1+tu*tv
                        float dl, dh; unpack2(d2, dl, dh);
                        u64 z = pack2(                               // z0 ~ -1/d seed
                            __uint_as_float(0xFEF311C3u - __float_as_uint(dl)),
                            __uint_as_float(0xFEF311C3u - __float_as_uint(dh)));
                        u64 e = f2_fma(d2, z, ONE2);                 // e = 1 + d*z
                        u64 p = f2_fma(e, e, e);                     // e + e^2
                        z     = f2_fma(z, p, z);                     // z(1+e+e^2): -1/d, err e^3
                        u64 pp = f2_mul(s2, z);                      // -s/d
                        acc[r][cp] = f2_fma(a2, pp, acc[r][cp]);     // a2 pre-negated
                    }
                }
            }
        }
    }

    // Stores come straight from the j-packed accumulators.
#pragma unroll
    for (int r = 0; r < 4; r++) {
        float o0, o1, o2, o3;
        unpack2(acc[r][0], o0, o1);
        unpack2(acc[r][1], o2, o3);
        int i = i0 + ty * 4 + r;
        *reinterpret_cast<float4*>(out + ((size_t)b * NN + i) * NN + j0 + tx * 4) =
            make_float4(o0, o1, o2, o3);
    }
}

extern "C" void kernel_launch(void* const* d_in, const int* in_sizes, int n_in,
                              void* d_out, int out_size)
{
    const float* cell = (const float*)d_in[0];
    const float* drug = (const float*)d_in[1];
    const float* w_q  = (const float*)d_in[2];
    const float* w_k  = (const float*)d_in[3];
    const float* bias = (const float*)d_in[4];
    const float* a    = (const float*)d_in[5];
    float* out = (float*)d_out;

    proj_kernel<<<(2 * BB * NN) / 4, 128>>>(cell, drug, w_q, w_k, bias);

    dim3 grid(NN / 64, NN / 64, BB);
    coattn_kernel<<<grid, 256>>>(a, out);
}